// round 3
// baseline (speedup 1.0000x reference)
#include <cuda_runtime.h>
#include <math.h>

// ---------------------------------------------------------------------------
// Problem constants
// ---------------------------------------------------------------------------
#define BB     8
#define HH     64
#define WW_    64
#define CC_    128
#define LL     4096           // HH*WW_
#define NHD    4
#define HD     32
#define WIN    8
#define SHIFT_ 4
#define NWIN   64             // windows per image
#define NTOK   64             // tokens per window
#define BL     32768          // BB*LL
#define BLC    4194304        // BL*CC_
#define SCALE_ 0.17677669529663687f   // 32^-0.5

// ---------------------------------------------------------------------------
// Scratch (device globals -- no allocation allowed)
// ---------------------------------------------------------------------------
__device__ float d_cat  [BL * 256];
__device__ float d_g    [BLC];
__device__ float d_xw   [BLC];
__device__ float d_qkv  [BL * 384];
__device__ float d_attn [BLC];
__device__ float d_proj [BLC];
__device__ float d_h2   [BLC];
__device__ float d_mlp  [BL * 512];
__device__ float d_local[BLC];
__device__ float d_off  [BB * 3 * LL];
__device__ float d_msk  [BB * 3 * LL];
__device__ float d_lg   [BLC];
__device__ float d_gg   [BLC];
__device__ float d_fu   [BLC];

// ---------------------------------------------------------------------------
// Generic fp32 GEMM: C = act(A*B + bias) (+ addsrc)
// A: MxK row-major, B: KxN row-major. M%128==0, N%128==0, K%8==0.
// BM=BN=128, BK=8, 256 threads, 8x8 per-thread microtile.
// act: 0 = none, 1 = exact GELU (erf)
// ---------------------------------------------------------------------------
__global__ __launch_bounds__(256) void sgemm_kernel(
    const float* __restrict__ A, const float* __restrict__ B,
    const float* __restrict__ bias, const float* __restrict__ addsrc,
    float* __restrict__ C, int M, int N, int K, int act)
{
    __shared__ float As[8][128];
    __shared__ float Bs[8][128];
    const int tid  = threadIdx.x;
    const int brow = blockIdx.y, bcol = blockIdx.x;
    const float* Ab = A + (size_t)brow * 128 * K;
    const float* Bb = B + bcol * 128;
    const int arow = tid >> 1,  acol = (tid & 1) << 2;
    const int brw  = tid >> 5,  bcl  = (tid & 31) << 2;
    const int ty   = tid >> 4,  tx   = tid & 15;

    float acc[8][8] = {};
    for (int k0 = 0; k0 < K; k0 += 8) {
        float4 av = *(const float4*)(Ab + (size_t)arow * K + k0 + acol);
        As[acol + 0][arow] = av.x;
        As[acol + 1][arow] = av.y;
        As[acol + 2][arow] = av.z;
        As[acol + 3][arow] = av.w;
        *(float4*)(&Bs[brw][bcl]) = *(const float4*)(Bb + (size_t)(k0 + brw) * N + bcl);
        __syncthreads();
        #pragma unroll
        for (int kk = 0; kk < 8; kk++) {
            float a[8], b[8];
            #pragma unroll
            for (int i = 0; i < 8; i++) a[i] = As[kk][ty * 8 + i];
            #pragma unroll
            for (int j = 0; j < 8; j++) b[j] = Bs[kk][tx * 8 + j];
            #pragma unroll
            for (int i = 0; i < 8; i++)
                #pragma unroll
                for (int j = 0; j < 8; j++)
                    acc[i][j] += a[i] * b[j];
        }
        __syncthreads();
    }

    #pragma unroll
    for (int i = 0; i < 8; i++) {
        size_t row = (size_t)brow * 128 + ty * 8 + i;
        float*       cp = C + row * N + bcol * 128 + tx * 8;
        const float* bp = bias + bcol * 128 + tx * 8;
        const float* ap = addsrc ? (addsrc + row * N + bcol * 128 + tx * 8) : nullptr;
        #pragma unroll
        for (int j = 0; j < 8; j++) {
            float v = acc[i][j] + bp[j];
            if (act == 1) v = 0.5f * v * (1.0f + erff(v * 0.70710678118654752f));
            if (ap) v += ap[j];
            cp[j] = v;
        }
    }
}

// ---------------------------------------------------------------------------
// Concat [xt | hx] -> d_cat (BL x 256)
// ---------------------------------------------------------------------------
__global__ void concat_kernel(const float* __restrict__ xt,
                              const float* __restrict__ hx,
                              float* __restrict__ cat)
{
    for (int idx = blockIdx.x * blockDim.x + threadIdx.x;
         idx < BL * 256; idx += gridDim.x * blockDim.x) {
        int m = idx >> 8, k = idx & 255;
        cat[idx] = (k < 128) ? xt[(size_t)m * 128 + k] : hx[(size_t)m * 128 + (k - 128)];
    }
}

// ---------------------------------------------------------------------------
// LayerNorm. windowed=1: gather with roll+window-partition permutation.
// One block (128 threads) per output row.
// ---------------------------------------------------------------------------
__global__ __launch_bounds__(128) void ln_kernel(
    const float* __restrict__ in, const float* __restrict__ gamma,
    const float* __restrict__ beta, float* __restrict__ out,
    int windowed, int shift)
{
    int m = blockIdx.x, c = threadIdx.x;
    int src = m;
    if (windowed) {
        int wdw = m >> 6, n = m & 63;
        int b = wdw >> 6, wi = wdw & 63;
        int h = ((wi >> 3) << 3) + (n >> 3);
        int x = ((wi & 7) << 3) + (n & 7);
        int hs = (h + shift) & 63, ws = (x + shift) & 63;
        src = b * LL + hs * 64 + ws;
    }
    float v = in[(size_t)src * 128 + c];

    __shared__ float red[8];
    float s = v;
    #pragma unroll
    for (int o = 16; o; o >>= 1) s += __shfl_down_sync(0xffffffffu, s, o);
    if ((c & 31) == 0) red[c >> 5] = s;
    __syncthreads();
    float mu = (red[0] + red[1] + red[2] + red[3]) * (1.0f / 128.0f);
    float d = v - mu;
    float s2 = d * d;
    #pragma unroll
    for (int o = 16; o; o >>= 1) s2 += __shfl_down_sync(0xffffffffu, s2, o);
    if ((c & 31) == 0) red[4 + (c >> 5)] = s2;
    __syncthreads();
    float var = (red[4] + red[5] + red[6] + red[7]) * (1.0f / 128.0f);
    out[(size_t)m * 128 + c] = d * rsqrtf(var + 1e-5f) * gamma[c] + beta[c];
}

// ---------------------------------------------------------------------------
// Window attention. grid=(512 windows, 4 heads), 64 threads (one per query).
// qkv layout per row: [q(0..127) | k(128..255) | v(256..383)], head*32+d.
// ---------------------------------------------------------------------------
__device__ __forceinline__ int region3(int p) { return p < 56 ? 0 : (p < 60 ? 1 : 2); }

__global__ __launch_bounds__(64) void attn_kernel(
    const float* __restrict__ qkv, const float* __restrict__ rp_d,
    float* __restrict__ out, int shift)
{
    __shared__ float qs[64][32], ks[64][32], vs[64][32];
    __shared__ float bias_s[225];
    const int w = blockIdx.x, head = blockIdx.y, tid = threadIdx.x;

    const float* base = qkv + (size_t)w * 64 * 384 + head * 32;
    for (int idx = tid; idx < 2048; idx += 64) {
        int r = idx >> 5, d = idx & 31;
        const float* p = base + (size_t)r * 384 + d;
        qs[r][d] = p[0] * SCALE_;
        ks[r][d] = p[128];
        vs[r][d] = p[256];
    }
    for (int idx = tid; idx < 225; idx += 64) bias_s[idx] = rp_d[idx * 4 + head];
    __syncthreads();

    const int i = tid;
    const int wi = w & 63, wh = wi >> 3, wwc = wi & 7;
    const int r1 = i >> 3, c1 = i & 7;
    int cnti = 0;
    if (shift)
        cnti = region3(wh * 8 + r1) * 3 + region3(wwc * 8 + c1);

    float4 q4[8];
    #pragma unroll
    for (int d = 0; d < 8; d++) q4[d] = *(const float4*)&qs[i][d * 4];

    float a[64];
    float mx = -1e30f;
    #pragma unroll
    for (int j = 0; j < 64; j++) {
        float s = 0.0f;
        #pragma unroll
        for (int d = 0; d < 8; d++) {
            float4 k4 = *(const float4*)&ks[j][d * 4];
            s += q4[d].x * k4.x + q4[d].y * k4.y + q4[d].z * k4.z + q4[d].w * k4.w;
        }
        int r2 = j >> 3, c2 = j & 7;
        s += bias_s[(r1 - r2 + 7) * 15 + (c1 - c2 + 7)];
        if (shift) {
            int cntj = region3(wh * 8 + r2) * 3 + region3(wwc * 8 + c2);
            if (cntj != cnti) s -= 100.0f;
        }
        a[j] = s;
        mx = fmaxf(mx, s);
    }
    float sum = 0.0f;
    #pragma unroll
    for (int j = 0; j < 64; j++) { a[j] = expf(a[j] - mx); sum += a[j]; }
    float inv = 1.0f / sum;

    float acc[32] = {};
    #pragma unroll
    for (int j = 0; j < 64; j++) {
        float aj = a[j] * inv;
        #pragma unroll
        for (int d = 0; d < 32; d++) acc[d] += aj * vs[j][d];
    }
    float* op = out + ((size_t)w * 64 + i) * 128 + head * 32;
    #pragma unroll
    for (int d = 0; d < 32; d++) op[d] = acc[d];
}

// ---------------------------------------------------------------------------
// Scatter-add: x[b, l_map(m), :] += proj[m, :]  (window-reverse + un-roll)
// ---------------------------------------------------------------------------
__global__ __launch_bounds__(128) void scatter_add_kernel(
    const float* __restrict__ proj, float* __restrict__ x, int shift)
{
    int m = blockIdx.x, c = threadIdx.x;
    int wdw = m >> 6, n = m & 63;
    int b = wdw >> 6, wi = wdw & 63;
    int h  = ((wi >> 3) << 3) + (n >> 3);
    int xx = ((wi & 7) << 3) + (n & 7);
    int hs = (h + shift) & 63, ws = (xx + shift) & 63;
    size_t dst = ((size_t)(b * LL + hs * 64 + ws)) * 128 + c;
    x[dst] += proj[(size_t)m * 128 + c];
}

// ---------------------------------------------------------------------------
// Offset/mask 1D conv (6 output channels, K=3, zero pad). One warp per (b,l).
// ---------------------------------------------------------------------------
__device__ __forceinline__ float sigmoidf_(float x) { return 1.0f / (1.0f + expf(-x)); }

__global__ __launch_bounds__(256) void offmask_conv_kernel(
    const float* __restrict__ xt,
    const float* __restrict__ off_w, const float* __restrict__ off_b,
    const float* __restrict__ msk_w, const float* __restrict__ msk_b,
    float* __restrict__ off_out, float* __restrict__ msk_out)
{
    __shared__ float ws[2304];           // 6 x 128 x 3
    int tid = threadIdx.x;
    for (int i = tid; i < 2304; i += 256)
        ws[i] = (i < 1152) ? off_w[i] : msk_w[i - 1152];
    __syncthreads();

    int warp = tid >> 5, lane = tid & 31;
    int pos = blockIdx.x * 8 + warp;     // b*L + l
    int b = pos >> 12, l = pos & 4095;

    float acc[6] = {};
    #pragma unroll
    for (int kk = 0; kk < 3; kk++) {
        int lp = l + kk - 1;
        if (lp < 0 || lp >= LL) continue;
        const float* xr = xt + ((size_t)b * LL + lp) * 128;
        #pragma unroll
        for (int cc = 0; cc < 4; cc++) {
            int c = lane + cc * 32;
            float v = xr[c];
            #pragma unroll
            for (int o = 0; o < 6; o++) acc[o] += v * ws[o * 384 + c * 3 + kk];
        }
    }
    #pragma unroll
    for (int o = 0; o < 6; o++)
        #pragma unroll
        for (int s = 16; s; s >>= 1) acc[o] += __shfl_down_sync(0xffffffffu, acc[o], s);
    if (lane == 0) {
        #pragma unroll
        for (int o = 0; o < 3; o++) {
            off_out[(size_t)b * 3 * LL + o * LL + l] = acc[o] + off_b[o];
            msk_out[(size_t)b * 3 * LL + o * LL + l] = sigmoidf_(acc[o + 3] + msk_b[o]);
        }
    }
}

// ---------------------------------------------------------------------------
// Deformable sampling -> local (stored (B,C,L) so the flat view IS (B*L, C))
// ---------------------------------------------------------------------------
__global__ __launch_bounds__(128) void deform_kernel(
    const float* __restrict__ xt, const float* __restrict__ off,
    const float* __restrict__ msk, float* __restrict__ local)
{
    int pos = blockIdx.x;
    int b = pos >> 12, l = pos & 4095;
    int c = threadIdx.x;
    float acc = 0.0f;
    #pragma unroll
    for (int k = 0; k < 3; k++) {
        float o = off[(size_t)b * 3 * LL + k * LL + l];
        float m = msk[(size_t)b * 3 * LL + k * LL + l];
        float p = fminf(fmaxf((float)l + o, 0.0f), 4095.0f);
        float fpf = floorf(p);
        int   fp = (int)fpf;
        int   cp = min(fp + 1, 4095);
        float al = p - fpf;
        float xf = xt[((size_t)b * LL + fp) * 128 + c];
        float xc = xt[((size_t)b * LL + cp) * 128 + c];
        acc += (xf * (1.0f - al) + xc * al) * m;
    }
    local[(size_t)b * CC_ * LL + (size_t)c * LL + l] = acc;
}

// ---------------------------------------------------------------------------
// fu-prep: lg = relu(lg * gg)
// ---------------------------------------------------------------------------
__global__ void mulrelu_kernel(float* __restrict__ lg, const float* __restrict__ gg)
{
    for (int i = blockIdx.x * blockDim.x + threadIdx.x;
         i < BLC; i += gridDim.x * blockDim.x) {
        float t = lg[i] * gg[i];
        lg[i] = t > 0.0f ? t : 0.0f;
    }
}

// ---------------------------------------------------------------------------
// LSTM-style gating -> hy
// ---------------------------------------------------------------------------
__global__ void gate_kernel(const float* __restrict__ fu,
                            const float* __restrict__ cx,
                            float* __restrict__ hy)
{
    for (int i = blockIdx.x * blockDim.x + threadIdx.x;
         i < BLC; i += gridDim.x * blockDim.x) {
        float f = fu[i];
        float g = sigmoidf_(f);
        float cell = tanhf(f);
        float cy = g * (cx[i] + cell);
        hy[i] = g * tanhf(cy);
    }
}

// ---------------------------------------------------------------------------
// Host orchestration
// ---------------------------------------------------------------------------
#define DSYM(p, s) do { void* _t = nullptr; cudaGetSymbolAddress(&_t, s); (p) = (float*)_t; } while (0)

extern "C" void kernel_launch(void* const* d_in, const int* in_sizes, int n_in,
                              void* d_out, int out_size)
{
    const float* xt    = (const float*)d_in[0];
    const float* hx    = (const float*)d_in[1];
    const float* cx    = (const float*)d_in[2];
    const float* red_w = (const float*)d_in[3];
    const float* red_b = (const float*)d_in[4];
    const float* n1g   = (const float*)d_in[5];
    const float* n1b   = (const float*)d_in[6];
    const float* qkvw  = (const float*)d_in[7];
    const float* qkvb  = (const float*)d_in[8];
    const float* rp    = (const float*)d_in[9];
    const float* pw    = (const float*)d_in[10];
    const float* pb    = (const float*)d_in[11];
    const float* n2g   = (const float*)d_in[12];
    const float* n2b   = (const float*)d_in[13];
    const float* f1w   = (const float*)d_in[14];
    const float* f1b   = (const float*)d_in[15];
    const float* f2w   = (const float*)d_in[16];
    const float* f2b   = (const float*)d_in[17];
    const float* off_w = (const float*)d_in[18];
    const float* off_b = (const float*)d_in[19];
    const float* msk_w = (const float*)d_in[20];
    const float* msk_b = (const float*)d_in[21];
    const float* lf_w  = (const float*)d_in[22];
    const float* lf_b  = (const float*)d_in[23];
    const float* gf_w  = (const float*)d_in[24];
    const float* gf_b  = (const float*)d_in[25];
    const float* ff_w  = (const float*)d_in[26];
    const float* ff_b  = (const float*)d_in[27];

    float *cat, *g, *xw, *qkv, *attn, *proj, *h2, *mlp, *local, *off, *msk, *lg, *gg, *fu;
    DSYM(cat, d_cat);   DSYM(g, d_g);       DSYM(xw, d_xw);   DSYM(qkv, d_qkv);
    DSYM(attn, d_attn); DSYM(proj, d_proj); DSYM(h2, d_h2);   DSYM(mlp, d_mlp);
    DSYM(local, d_local); DSYM(off, d_off); DSYM(msk, d_msk);
    DSYM(lg, d_lg);     DSYM(gg, d_gg);     DSYM(fu, d_fu);

    // global branch: g = [xt|hx] @ red_w + red_b
    concat_kernel<<<2048, 512>>>(xt, hx, cat);
    sgemm_kernel<<<dim3(1, 256), 256>>>(cat, red_w, red_b, nullptr, g, BL, 128, 256, 0);

    for (int dep = 0; dep < 2; dep++) {
        int shift = dep ? SHIFT_ : 0;
        const float* qkvw_d = qkvw + (size_t)dep * 128 * 384;
        const float* qkvb_d = qkvb + dep * 384;
        const float* rp_d   = rp   + dep * 225 * 4;
        const float* pw_d   = pw   + (size_t)dep * 128 * 128;
        const float* pb_d   = pb   + dep * 128;
        const float* f1w_d  = f1w  + (size_t)dep * 128 * 512;
        const float* f1b_d  = f1b  + dep * 512;
        const float* f2w_d  = f2w  + (size_t)dep * 512 * 128;
        const float* f2b_d  = f2b  + dep * 128;

        ln_kernel<<<BL, 128>>>(g, n1g + dep * 128, n1b + dep * 128, xw, 1, shift);
        sgemm_kernel<<<dim3(3, 256), 256>>>(xw, qkvw_d, qkvb_d, nullptr, qkv, BL, 384, 128, 0);
        attn_kernel<<<dim3(512, 4), 64>>>(qkv, rp_d, attn, shift);
        sgemm_kernel<<<dim3(1, 256), 256>>>(attn, pw_d, pb_d, nullptr, proj, BL, 128, 128, 0);
        scatter_add_kernel<<<BL, 128>>>(proj, g, shift);
        ln_kernel<<<BL, 128>>>(g, n2g + dep * 128, n2b + dep * 128, h2, 0, 0);
        sgemm_kernel<<<dim3(4, 256), 256>>>(h2, f1w_d, f1b_d, nullptr, mlp, BL, 512, 128, 1);
        sgemm_kernel<<<dim3(1, 256), 256>>>(mlp, f2w_d, f2b_d, g, g, BL, 128, 512, 0);
    }

    // local branch (deformable 1D conv)
    offmask_conv_kernel<<<4096, 256>>>(xt, off_w, off_b, msk_w, msk_b, off, msk);
    deform_kernel<<<BL, 128>>>(xt, off, msk, local);

    // fusion + gating
    sgemm_kernel<<<dim3(1, 256), 256>>>(local, lf_w, lf_b, nullptr, lg, BL, 128, 128, 0);
    sgemm_kernel<<<dim3(1, 256), 256>>>(g,     gf_w, gf_b, nullptr, gg, BL, 128, 128, 0);
    mulrelu_kernel<<<4096, 512>>>(lg, gg);
    sgemm_kernel<<<dim3(1, 256), 256>>>(lg, ff_w, ff_b, nullptr, fu, BL, 128, 128, 0);
    gate_kernel<<<4096, 512>>>(fu, cx, (float*)d_out);
}

// round 4
// speedup vs baseline: 2.1458x; 2.1458x over previous
#include <cuda_runtime.h>
#include <math.h>
#include <stdint.h>

// ---------------------------------------------------------------------------
// Problem constants
// ---------------------------------------------------------------------------
#define BB     8
#define LL     4096
#define CC_    128
#define SHIFT_ 4
#define BL     32768          // BB*LL
#define BLC    4194304        // BL*CC_
#define SCALE_ 0.17677669529663687f   // 32^-0.5

// ---------------------------------------------------------------------------
// Scratch (device globals -- no allocation allowed)
// ---------------------------------------------------------------------------
__device__ float d_g    [BLC];
__device__ float d_xw   [BLC];
__device__ float d_qkv  [BL * 384];
__device__ float d_attn [BLC];
__device__ float d_proj [BLC];
__device__ float d_h2   [BLC];
__device__ float d_mlp  [BL * 512];
__device__ float d_local[BLC];
__device__ float d_off  [BB * 3 * LL];
__device__ float d_msk  [BB * 3 * LL];
__device__ float d_lg   [BLC];
__device__ float d_fu   [BLC];

// ---------------------------------------------------------------------------
// tf32 helpers
// ---------------------------------------------------------------------------
__device__ __forceinline__ float to_tf32(float x) {
    uint32_t u;
    asm("cvt.rna.tf32.f32 %0, %1;" : "=r"(u) : "f"(x));
    return __uint_as_float(u);
}

__device__ __forceinline__ void mma_tf32(float* d, const uint32_t* a,
                                         uint32_t b0, uint32_t b1) {
    asm volatile(
        "mma.sync.aligned.m16n8k8.row.col.f32.tf32.tf32.f32 "
        "{%0,%1,%2,%3}, {%4,%5,%6,%7}, {%8,%9}, {%0,%1,%2,%3};\n"
        : "+f"(d[0]), "+f"(d[1]), "+f"(d[2]), "+f"(d[3])
        : "r"(a[0]), "r"(a[1]), "r"(a[2]), "r"(a[3]), "r"(b0), "r"(b1));
}

__device__ __forceinline__ float sigmoidf_(float x) { return 1.0f / (1.0f + expf(-x)); }

// ---------------------------------------------------------------------------
// Tensor-core tf32 GEMM: C = epi(A*B + bias, aux)
// A: MxK row-major (optionally split at Ksplit between A and A2, each with
// row stride Ksplit / K-Ksplit -- used to fuse the [xt|hx] concat).
// B: KxN row-major. M%128==0, N%128==0, K%32==0.
// Block tile 128x128x32, 256 threads (8 warps, warp tile 32x64, m16n8k8).
// mode: 0 none | 1 gelu | 2 +aux | 3 relu(v*aux) | 4 LSTM gate with aux=cx
// ---------------------------------------------------------------------------
__global__ __launch_bounds__(256, 2) void tgemm(
    const float* __restrict__ A, const float* __restrict__ A2,
    const float* __restrict__ Bw,
    const float* __restrict__ bias, const float* __restrict__ aux,
    float* __restrict__ C, int M, int N, int K, int Ksplit, int mode)
{
    __shared__ float As[128][36];   // pad 36: frag bank = (4r+c)%32, conflict-free
    __shared__ float Bs[32][136];   // pad 136: frag bank = (8k+n)%32, conflict-free

    const int tid  = threadIdx.x;
    const int brow = blockIdx.y, bcol = blockIdx.x;
    const int warp = tid >> 5, lane = tid & 31;
    const int wm = (warp >> 1) << 5;      // 0,32,64,96
    const int wn = (warp & 1) << 6;       // 0,64
    const int qid = lane >> 2, rid = lane & 3;
    const int lda2 = K - Ksplit;

    float acc[2][8][4];
    #pragma unroll
    for (int i = 0; i < 2; i++)
        #pragma unroll
        for (int j = 0; j < 8; j++)
            #pragma unroll
            for (int h = 0; h < 4; h++) acc[i][j][h] = 0.0f;

    float4 ra[4], rb[4];
    // prologue global load (k0 = 0)
    #pragma unroll
    for (int p = 0; p < 4; p++) {
        int id = tid + (p << 8);
        int row = id >> 3, cv = (id & 7) << 2;
        size_t m = (size_t)brow * 128 + row;
        ra[p] = (cv < Ksplit) ? *(const float4*)(A + m * Ksplit + cv)
                              : *(const float4*)(A2 + m * lda2 + cv - Ksplit);
        int kr = id >> 5, cn = (id & 31) << 2;
        rb[p] = *(const float4*)(Bw + (size_t)kr * N + bcol * 128 + cn);
    }

    for (int k0 = 0; k0 < K; k0 += 32) {
        __syncthreads();
        #pragma unroll
        for (int p = 0; p < 4; p++) {
            int id = tid + (p << 8);
            int row = id >> 3, cv = (id & 7) << 2;
            As[row][cv + 0] = to_tf32(ra[p].x);
            As[row][cv + 1] = to_tf32(ra[p].y);
            As[row][cv + 2] = to_tf32(ra[p].z);
            As[row][cv + 3] = to_tf32(ra[p].w);
            int kr = id >> 5, cn = (id & 31) << 2;
            Bs[kr][cn + 0] = to_tf32(rb[p].x);
            Bs[kr][cn + 1] = to_tf32(rb[p].y);
            Bs[kr][cn + 2] = to_tf32(rb[p].z);
            Bs[kr][cn + 3] = to_tf32(rb[p].w);
        }
        __syncthreads();

        if (k0 + 32 < K) {              // prefetch next tile (overlaps compute)
            int kn = k0 + 32;
            #pragma unroll
            for (int p = 0; p < 4; p++) {
                int id = tid + (p << 8);
                int row = id >> 3, cv = (id & 7) << 2;
                size_t m = (size_t)brow * 128 + row;
                int k = kn + cv;
                ra[p] = (k < Ksplit) ? *(const float4*)(A + m * Ksplit + k)
                                     : *(const float4*)(A2 + m * lda2 + k - Ksplit);
                int kr = id >> 5, cn = (id & 31) << 2;
                rb[p] = *(const float4*)(Bw + (size_t)(kn + kr) * N + bcol * 128 + cn);
            }
        }

        #pragma unroll
        for (int ks = 0; ks < 32; ks += 8) {
            uint32_t af[2][4];
            #pragma unroll
            for (int i = 0; i < 2; i++) {
                int r0 = wm + i * 16 + qid;
                af[i][0] = __float_as_uint(As[r0    ][ks + rid    ]);
                af[i][1] = __float_as_uint(As[r0 + 8][ks + rid    ]);
                af[i][2] = __float_as_uint(As[r0    ][ks + rid + 4]);
                af[i][3] = __float_as_uint(As[r0 + 8][ks + rid + 4]);
            }
            #pragma unroll
            for (int j = 0; j < 8; j++) {
                uint32_t b0 = __float_as_uint(Bs[ks + rid    ][wn + j * 8 + qid]);
                uint32_t b1 = __float_as_uint(Bs[ks + rid + 4][wn + j * 8 + qid]);
                mma_tf32(acc[0][j], af[0], b0, b1);
                mma_tf32(acc[1][j], af[1], b0, b1);
            }
        }
    }

    // epilogue
    #pragma unroll
    for (int i = 0; i < 2; i++) {
        #pragma unroll
        for (int j = 0; j < 8; j++) {
            int col = bcol * 128 + wn + j * 8 + rid * 2;
            float2 bb = *(const float2*)(bias + col);
            #pragma unroll
            for (int h = 0; h < 2; h++) {
                size_t row = (size_t)brow * 128 + wm + i * 16 + qid + h * 8;
                float v0 = acc[i][j][h * 2 + 0] + bb.x;
                float v1 = acc[i][j][h * 2 + 1] + bb.y;
                if (mode == 1) {
                    v0 = 0.5f * v0 * (1.0f + erff(v0 * 0.70710678118654752f));
                    v1 = 0.5f * v1 * (1.0f + erff(v1 * 0.70710678118654752f));
                } else if (mode >= 2) {
                    float2 ax = *(const float2*)(aux + row * N + col);
                    if (mode == 2) { v0 += ax.x; v1 += ax.y; }
                    else if (mode == 3) {
                        v0 *= ax.x; v1 *= ax.y;
                        v0 = v0 > 0.0f ? v0 : 0.0f;
                        v1 = v1 > 0.0f ? v1 : 0.0f;
                    } else {  // mode 4: LSTM gate, ax = cx
                        float g0 = sigmoidf_(v0), g1 = sigmoidf_(v1);
                        float cy0 = g0 * (ax.x + tanhf(v0));
                        float cy1 = g1 * (ax.y + tanhf(v1));
                        v0 = g0 * tanhf(cy0);
                        v1 = g1 * tanhf(cy1);
                    }
                }
                *(float2*)(C + row * N + col) = make_float2(v0, v1);
            }
        }
    }
}

// ---------------------------------------------------------------------------
// LayerNorm. windowed=1: gather with roll+window-partition permutation.
// ---------------------------------------------------------------------------
__global__ __launch_bounds__(128) void ln_kernel(
    const float* __restrict__ in, const float* __restrict__ gamma,
    const float* __restrict__ beta, float* __restrict__ out,
    int windowed, int shift)
{
    int m = blockIdx.x, c = threadIdx.x;
    int src = m;
    if (windowed) {
        int wdw = m >> 6, n = m & 63;
        int b = wdw >> 6, wi = wdw & 63;
        int h = ((wi >> 3) << 3) + (n >> 3);
        int x = ((wi & 7) << 3) + (n & 7);
        int hs = (h + shift) & 63, ws = (x + shift) & 63;
        src = b * LL + hs * 64 + ws;
    }
    float v = in[(size_t)src * 128 + c];

    __shared__ float red[8];
    float s = v;
    #pragma unroll
    for (int o = 16; o; o >>= 1) s += __shfl_down_sync(0xffffffffu, s, o);
    if ((c & 31) == 0) red[c >> 5] = s;
    __syncthreads();
    float mu = (red[0] + red[1] + red[2] + red[3]) * (1.0f / 128.0f);
    float d = v - mu;
    float s2 = d * d;
    #pragma unroll
    for (int o = 16; o; o >>= 1) s2 += __shfl_down_sync(0xffffffffu, s2, o);
    if ((c & 31) == 0) red[4 + (c >> 5)] = s2;
    __syncthreads();
    float var = (red[4] + red[5] + red[6] + red[7]) * (1.0f / 128.0f);
    out[(size_t)m * 128 + c] = d * rsqrtf(var + 1e-5f) * gamma[c] + beta[c];
}

// ---------------------------------------------------------------------------
// Window attention. grid=(512 windows, 4 heads), 64 threads (one per query).
// ---------------------------------------------------------------------------
__device__ __forceinline__ int region3(int p) { return p < 56 ? 0 : (p < 60 ? 1 : 2); }

__global__ __launch_bounds__(64) void attn_kernel(
    const float* __restrict__ qkv, const float* __restrict__ rp_d,
    float* __restrict__ out, int shift)
{
    __shared__ float qs[64][32], ks[64][32], vs[64][32];
    __shared__ float bias_s[225];
    const int w = blockIdx.x, head = blockIdx.y, tid = threadIdx.x;

    const float* base = qkv + (size_t)w * 64 * 384 + head * 32;
    for (int idx = tid; idx < 2048; idx += 64) {
        int r = idx >> 5, d = idx & 31;
        const float* p = base + (size_t)r * 384 + d;
        qs[r][d] = p[0] * SCALE_;
        ks[r][d] = p[128];
        vs[r][d] = p[256];
    }
    for (int idx = tid; idx < 225; idx += 64) bias_s[idx] = rp_d[idx * 4 + head];
    __syncthreads();

    const int i = tid;
    const int wi = w & 63, wh = wi >> 3, wwc = wi & 7;
    const int r1 = i >> 3, c1 = i & 7;
    int cnti = 0;
    if (shift)
        cnti = region3(wh * 8 + r1) * 3 + region3(wwc * 8 + c1);

    float4 q4[8];
    #pragma unroll
    for (int d = 0; d < 8; d++) q4[d] = *(const float4*)&qs[i][d * 4];

    float a[64];
    float mx = -1e30f;
    #pragma unroll
    for (int j = 0; j < 64; j++) {
        float s = 0.0f;
        #pragma unroll
        for (int d = 0; d < 8; d++) {
            float4 k4 = *(const float4*)&ks[j][d * 4];
            s += q4[d].x * k4.x + q4[d].y * k4.y + q4[d].z * k4.z + q4[d].w * k4.w;
        }
        int r2 = j >> 3, c2 = j & 7;
        s += bias_s[(r1 - r2 + 7) * 15 + (c1 - c2 + 7)];
        if (shift) {
            int cntj = region3(wh * 8 + r2) * 3 + region3(wwc * 8 + c2);
            if (cntj != cnti) s -= 100.0f;
        }
        a[j] = s;
        mx = fmaxf(mx, s);
    }
    float sum = 0.0f;
    #pragma unroll
    for (int j = 0; j < 64; j++) { a[j] = expf(a[j] - mx); sum += a[j]; }
    float inv = 1.0f / sum;

    float acc[32] = {};
    #pragma unroll
    for (int j = 0; j < 64; j++) {
        float aj = a[j] * inv;
        #pragma unroll
        for (int d = 0; d < 32; d++) acc[d] += aj * vs[j][d];
    }
    float* op = out + ((size_t)w * 64 + i) * 128 + head * 32;
    #pragma unroll
    for (int d = 0; d < 32; d++) op[d] = acc[d];
}

// ---------------------------------------------------------------------------
// Scatter-add: x[b, l_map(m), :] += proj[m, :]  (window-reverse + un-roll)
// ---------------------------------------------------------------------------
__global__ __launch_bounds__(128) void scatter_add_kernel(
    const float* __restrict__ proj, float* __restrict__ x, int shift)
{
    int m = blockIdx.x, c = threadIdx.x;
    int wdw = m >> 6, n = m & 63;
    int b = wdw >> 6, wi = wdw & 63;
    int h  = ((wi >> 3) << 3) + (n >> 3);
    int xx = ((wi & 7) << 3) + (n & 7);
    int hs = (h + shift) & 63, ws = (xx + shift) & 63;
    size_t dst = ((size_t)(b * LL + hs * 64 + ws)) * 128 + c;
    x[dst] += proj[(size_t)m * 128 + c];
}

// ---------------------------------------------------------------------------
// Offset/mask 1D conv (6 output channels, K=3, zero pad). One warp per (b,l).
// ---------------------------------------------------------------------------
__global__ __launch_bounds__(256) void offmask_conv_kernel(
    const float* __restrict__ xt,
    const float* __restrict__ off_w, const float* __restrict__ off_b,
    const float* __restrict__ msk_w, const float* __restrict__ msk_b,
    float* __restrict__ off_out, float* __restrict__ msk_out)
{
    __shared__ float ws[2304];           // 6 x 128 x 3
    int tid = threadIdx.x;
    for (int i = tid; i < 2304; i += 256)
        ws[i] = (i < 1152) ? off_w[i] : msk_w[i - 1152];
    __syncthreads();

    int warp = tid >> 5, lane = tid & 31;
    int pos = blockIdx.x * 8 + warp;     // b*L + l
    int b = pos >> 12, l = pos & 4095;

    float acc[6] = {};
    #pragma unroll
    for (int kk = 0; kk < 3; kk++) {
        int lp = l + kk - 1;
        if (lp < 0 || lp >= LL) continue;
        const float* xr = xt + ((size_t)b * LL + lp) * 128;
        #pragma unroll
        for (int cc = 0; cc < 4; cc++) {
            int c = lane + cc * 32;
            float v = xr[c];
            #pragma unroll
            for (int o = 0; o < 6; o++) acc[o] += v * ws[o * 384 + c * 3 + kk];
        }
    }
    #pragma unroll
    for (int o = 0; o < 6; o++)
        #pragma unroll
        for (int s = 16; s; s >>= 1) acc[o] += __shfl_down_sync(0xffffffffu, acc[o], s);
    if (lane == 0) {
        #pragma unroll
        for (int o = 0; o < 3; o++) {
            off_out[(size_t)b * 3 * LL + o * LL + l] = acc[o] + off_b[o];
            msk_out[(size_t)b * 3 * LL + o * LL + l] = sigmoidf_(acc[o + 3] + msk_b[o]);
        }
    }
}

// ---------------------------------------------------------------------------
// Deformable sampling -> local (stored (B,C,L) so the flat view IS (B*L, C))
// ---------------------------------------------------------------------------
__global__ __launch_bounds__(128) void deform_kernel(
    const float* __restrict__ xt, const float* __restrict__ off,
    const float* __restrict__ msk, float* __restrict__ local)
{
    int pos = blockIdx.x;
    int b = pos >> 12, l = pos & 4095;
    int c = threadIdx.x;
    float acc = 0.0f;
    #pragma unroll
    for (int k = 0; k < 3; k++) {
        float o = off[(size_t)b * 3 * LL + k * LL + l];
        float m = msk[(size_t)b * 3 * LL + k * LL + l];
        float p = fminf(fmaxf((float)l + o, 0.0f), 4095.0f);
        float fpf = floorf(p);
        int   fp = (int)fpf;
        int   cp = min(fp + 1, 4095);
        float al = p - fpf;
        float xf = xt[((size_t)b * LL + fp) * 128 + c];
        float xc = xt[((size_t)b * LL + cp) * 128 + c];
        acc += (xf * (1.0f - al) + xc * al) * m;
    }
    local[(size_t)b * CC_ * LL + (size_t)c * LL + l] = acc;
}

// ---------------------------------------------------------------------------
// Host orchestration
// ---------------------------------------------------------------------------
#define DSYM(p, s) do { void* _t = nullptr; cudaGetSymbolAddress(&_t, s); (p) = (float*)_t; } while (0)

extern "C" void kernel_launch(void* const* d_in, const int* in_sizes, int n_in,
                              void* d_out, int out_size)
{
    const float* xt    = (const float*)d_in[0];
    const float* hx    = (const float*)d_in[1];
    const float* cx    = (const float*)d_in[2];
    const float* red_w = (const float*)d_in[3];
    const float* red_b = (const float*)d_in[4];
    const float* n1g   = (const float*)d_in[5];
    const float* n1b   = (const float*)d_in[6];
    const float* qkvw  = (const float*)d_in[7];
    const float* qkvb  = (const float*)d_in[8];
    const float* rp    = (const float*)d_in[9];
    const float* pw    = (const float*)d_in[10];
    const float* pb    = (const float*)d_in[11];
    const float* n2g   = (const float*)d_in[12];
    const float* n2b   = (const float*)d_in[13];
    const float* f1w   = (const float*)d_in[14];
    const float* f1b   = (const float*)d_in[15];
    const float* f2w   = (const float*)d_in[16];
    const float* f2b   = (const float*)d_in[17];
    const float* off_w = (const float*)d_in[18];
    const float* off_b = (const float*)d_in[19];
    const float* msk_w = (const float*)d_in[20];
    const float* msk_b = (const float*)d_in[21];
    const float* lf_w  = (const float*)d_in[22];
    const float* lf_b  = (const float*)d_in[23];
    const float* gf_w  = (const float*)d_in[24];
    const float* gf_b  = (const float*)d_in[25];
    const float* ff_w  = (const float*)d_in[26];
    const float* ff_b  = (const float*)d_in[27];

    float *g, *xw, *qkv, *attn, *proj, *h2, *mlp, *local, *off, *msk, *lg, *fu;
    DSYM(g, d_g);       DSYM(xw, d_xw);   DSYM(qkv, d_qkv);
    DSYM(attn, d_attn); DSYM(proj, d_proj); DSYM(h2, d_h2);   DSYM(mlp, d_mlp);
    DSYM(local, d_local); DSYM(off, d_off); DSYM(msk, d_msk);
    DSYM(lg, d_lg);     DSYM(fu, d_fu);

    // local branch (independent of global branch -- launch first)
    offmask_conv_kernel<<<4096, 256>>>(xt, off_w, off_b, msk_w, msk_b, off, msk);
    deform_kernel<<<BL, 128>>>(xt, off, msk, local);

    // global branch: g = [xt|hx] @ red_w + red_b   (concat fused via K-split)
    tgemm<<<dim3(1, 256), 256>>>(xt, hx, red_w, red_b, nullptr, g,
                                 BL, 128, 256, 128, 0);

    for (int dep = 0; dep < 2; dep++) {
        int shift = dep ? SHIFT_ : 0;
        const float* qkvw_d = qkvw + (size_t)dep * 128 * 384;
        const float* qkvb_d = qkvb + dep * 384;
        const float* rp_d   = rp   + dep * 225 * 4;
        const float* pw_d   = pw   + (size_t)dep * 128 * 128;
        const float* pb_d   = pb   + dep * 128;
        const float* f1w_d  = f1w  + (size_t)dep * 128 * 512;
        const float* f1b_d  = f1b  + dep * 512;
        const float* f2w_d  = f2w  + (size_t)dep * 512 * 128;
        const float* f2b_d  = f2b  + dep * 128;

        ln_kernel<<<BL, 128>>>(g, n1g + dep * 128, n1b + dep * 128, xw, 1, shift);
        tgemm<<<dim3(3, 256), 256>>>(xw, xw, qkvw_d, qkvb_d, nullptr, qkv,
                                     BL, 384, 128, 128, 0);
        attn_kernel<<<dim3(512, 4), 64>>>(qkv, rp_d, attn, shift);
        tgemm<<<dim3(1, 256), 256>>>(attn, attn, pw_d, pb_d, nullptr, proj,
                                     BL, 128, 128, 128, 0);
        scatter_add_kernel<<<BL, 128>>>(proj, g, shift);
        ln_kernel<<<BL, 128>>>(g, n2g + dep * 128, n2b + dep * 128, h2, 0, 0);
        tgemm<<<dim3(4, 256), 256>>>(h2, h2, f1w_d, f1b_d, nullptr, mlp,
                                     BL, 512, 128, 128, 1);
        tgemm<<<dim3(1, 256), 256>>>(mlp, mlp, f2w_d, f2b_d, g, g,
                                     BL, 128, 512, 512, 2);
    }

    // fusion + gating (mulrelu fused into gf epilogue, gate into ff epilogue)
    tgemm<<<dim3(1, 256), 256>>>(local, local, lf_w, lf_b, nullptr, lg,
                                 BL, 128, 128, 128, 0);
    tgemm<<<dim3(1, 256), 256>>>(g, g, gf_w, gf_b, lg, fu,
                                 BL, 128, 128, 128, 3);
    tgemm<<<dim3(1, 256), 256>>>(fu, fu, ff_w, ff_b, cx, (float*)d_out,
                                 BL, 128, 128, 128, 4);
}